// round 5
// baseline (speedup 1.0000x reference)
#include <cuda_runtime.h>

#define NIN 7
#define H   32
#define TPB 128   // threads per block
#define SPT 4     // samples per thread

typedef unsigned long long u64;

// ---- f32x2 packed helpers (sm_100+ PTX) ----
__device__ __forceinline__ u64 pk2(float a, float b) {
    u64 r; asm("mov.b64 %0, {%1, %2};" : "=l"(r) : "f"(a), "f"(b)); return r;
}
__device__ __forceinline__ float2 upk2(u64 v) {
    float2 f; asm("mov.b64 {%0, %1}, %2;" : "=f"(f.x), "=f"(f.y) : "l"(v)); return f;
}
__device__ __forceinline__ u64 ffma2(u64 a, u64 b, u64 c) {
    u64 r; asm("fma.rn.f32x2 %0, %1, %2, %3;" : "=l"(r) : "l"(a), "l"(b), "l"(c)); return r;
}

// Single-instruction MUFU.TANH (sm_75+): 1 SFU op, zero fma-pipe ops.
__device__ __forceinline__ float tanh_approx(float x) {
    float r; asm("tanh.approx.f32 %0, %1;" : "=f"(r) : "f"(x)); return r;
}

__global__ __launch_bounds__(TPB, 4)
void WarpTileMLP_kernel(const float* __restrict__ q,
                        const float* __restrict__ w0, const float* __restrict__ b0,
                        const float* __restrict__ w1, const float* __restrict__ b1,
                        const float* __restrict__ w2, const float* __restrict__ b2,
                        float* __restrict__ out)
{
    // Weights transposed to [i][h]: one 128-bit broadcast shared load
    // = 2 f32x2 weight pairs (4 adjacent hidden units).
    __shared__ __align__(16) float sw0[NIN * H];   // sw0[i*32 + h] = w0[h][i]
    __shared__ __align__(16) float sw1[H * H];     // sw1[i*32 + h] = w1[h][i]
    __shared__ __align__(16) float sb0[H];
    __shared__ __align__(16) float sb1[H];
    __shared__ __align__(16) float sw2[H];
    __shared__ float sb2s;
    // z for samples C,D: zcd[i][tid] = (zC[i], zD[i]). Each thread touches only
    // its own column -> no sync needed, conflict-free 8B-stride access. 32KB.
    __shared__ u64 zcd[H][TPB];

    const int tid = threadIdx.x;
    for (int k = tid; k < NIN * H; k += TPB) {
        int i = k >> 5, h = k & 31;
        sw0[k] = w0[h * NIN + i];
    }
    for (int k = tid; k < H * H; k += TPB) {
        int i = k >> 5, h = k & 31;
        sw1[k] = w1[h * H + i];
    }
    if (tid < H) { sb0[tid] = b0[tid]; sb1[tid] = b1[tid]; sw2[tid] = w2[tid]; }
    if (tid == 0) sb2s = b2[0];
    __syncthreads();

    const long t = (long)blockIdx.x * TPB + tid;

    // 4 samples = 28 contiguous floats = 7 aligned float4 loads.
    const float4* qv4 = (const float4*)q;
    float v[SPT * NIN];
#pragma unroll
    for (int j = 0; j < 7; ++j) {
        float4 p = __ldg(&qv4[t * 7 + j]);
        v[4 * j] = p.x; v[4 * j + 1] = p.y; v[4 * j + 2] = p.z; v[4 * j + 3] = p.w;
    }
    // v[s*7 + i] = input i of sample s (s=0:A, 1:B, 2:C, 3:D)

    const ulonglong2* sw0v = (const ulonglong2*)sw0;  // [i*8 + c] : 4 hidden units
    const ulonglong2* sw1v = (const ulonglong2*)sw1;
    const u64* sb0p = (const u64*)sb0;
    const u64* sb1p = (const u64*)sb1;
    const u64* sw2p = (const u64*)sw2;

    // ------------ Layer 0: 7 -> 32 for 4 samples, in quarters of 8 ----------
    float zA[H], zB[H];
#pragma unroll
    for (int qtr = 0; qtr < 4; ++qtr) {
        u64 acc[SPT][4];    // [sample][output-pair], 16 u64 = 32 regs
#pragma unroll
        for (int p = 0; p < 4; ++p) {
            u64 bb = sb0p[qtr * 4 + p];
#pragma unroll
            for (int s = 0; s < SPT; ++s) acc[s][p] = bb;
        }
#pragma unroll
        for (int i = 0; i < NIN; ++i) {
            u64 xs[SPT];
#pragma unroll
            for (int s = 0; s < SPT; ++s) xs[s] = pk2(v[s * 7 + i], v[s * 7 + i]);
#pragma unroll
            for (int c = 0; c < 2; ++c) {
                ulonglong2 w = sw0v[i * 8 + qtr * 2 + c];
#pragma unroll
                for (int s = 0; s < SPT; ++s) {
                    acc[s][2 * c]     = ffma2(w.x, xs[s], acc[s][2 * c]);
                    acc[s][2 * c + 1] = ffma2(w.y, xs[s], acc[s][2 * c + 1]);
                }
            }
        }
        // tanh: A,B -> registers; C,D -> shared (own column, no sync needed)
#pragma unroll
        for (int p = 0; p < 4; ++p) {
            int h0 = qtr * 8 + 2 * p;
            float2 a = upk2(acc[0][p]);
            zA[h0] = tanh_approx(a.x); zA[h0 + 1] = tanh_approx(a.y);
            float2 b = upk2(acc[1][p]);
            zB[h0] = tanh_approx(b.x); zB[h0 + 1] = tanh_approx(b.y);
            float2 c2 = upk2(acc[2][p]);
            float2 d2 = upk2(acc[3][p]);
            zcd[h0][tid]     = pk2(tanh_approx(c2.x), tanh_approx(d2.x));
            zcd[h0 + 1][tid] = pk2(tanh_approx(c2.y), tanh_approx(d2.y));
        }
    }

    // ------- Layer 1 (quartered) fused with Layer 2, 4 samples at once ------
    u64 o[SPT];
#pragma unroll
    for (int s = 0; s < SPT; ++s) o[s] = pk2(0.0f, 0.0f);

#pragma unroll
    for (int qtr = 0; qtr < 4; ++qtr) {
        u64 a1[SPT][4];     // 16 u64 = 32 regs
#pragma unroll
        for (int p = 0; p < 4; ++p) {
            u64 bb = sb1p[qtr * 4 + p];
#pragma unroll
            for (int s = 0; s < SPT; ++s) a1[s][p] = bb;
        }
#pragma unroll
        for (int i = 0; i < H; ++i) {
            u64 xa = pk2(zA[i], zA[i]);
            u64 xb = pk2(zB[i], zB[i]);
            float2 cdv = upk2(zcd[i][tid]);
            u64 xc = pk2(cdv.x, cdv.x);
            u64 xd = pk2(cdv.y, cdv.y);
#pragma unroll
            for (int c = 0; c < 2; ++c) {
                ulonglong2 w = sw1v[i * 8 + qtr * 2 + c];
                a1[0][2 * c]     = ffma2(w.x, xa, a1[0][2 * c]);
                a1[0][2 * c + 1] = ffma2(w.y, xa, a1[0][2 * c + 1]);
                a1[1][2 * c]     = ffma2(w.x, xb, a1[1][2 * c]);
                a1[1][2 * c + 1] = ffma2(w.y, xb, a1[1][2 * c + 1]);
                a1[2][2 * c]     = ffma2(w.x, xc, a1[2][2 * c]);
                a1[2][2 * c + 1] = ffma2(w.y, xc, a1[2][2 * c + 1]);
                a1[3][2 * c]     = ffma2(w.x, xd, a1[3][2 * c]);
                a1[3][2 * c + 1] = ffma2(w.y, xd, a1[3][2 * c + 1]);
            }
        }
        // tanh + layer-2 partial dot (a1 dies here)
#pragma unroll
        for (int p = 0; p < 4; ++p) {
            u64 wp = sw2p[qtr * 4 + p];
#pragma unroll
            for (int s = 0; s < SPT; ++s) {
                float2 a = upk2(a1[s][p]);
                u64 z1 = pk2(tanh_approx(a.x), tanh_approx(a.y));
                o[s] = ffma2(wp, z1, o[s]);
            }
        }
    }

    const float bias2 = sb2s;
    float4 r;
    { float2 a = upk2(o[0]); r.x = a.x + a.y + bias2; }
    { float2 a = upk2(o[1]); r.y = a.x + a.y + bias2; }
    { float2 a = upk2(o[2]); r.z = a.x + a.y + bias2; }
    { float2 a = upk2(o[3]); r.w = a.x + a.y + bias2; }

    ((float4*)out)[t] = r;
}

extern "C" void kernel_launch(void* const* d_in, const int* in_sizes, int n_in,
                              void* d_out, int out_size)
{
    const float* q  = (const float*)d_in[0];
    const float* w0 = (const float*)d_in[1];
    const float* b0 = (const float*)d_in[2];
    const float* w1 = (const float*)d_in[3];
    const float* b1 = (const float*)d_in[4];
    const float* w2 = (const float*)d_in[5];
    const float* b2 = (const float*)d_in[6];
    float* out = (float*)d_out;

    const int B = in_sizes[0] / NIN;              // 2097152
    const int blocks = B / (TPB * SPT);           // 4096

    WarpTileMLP_kernel<<<blocks, TPB>>>(q, w0, b0, w1, b1, w2, b2, out);
}

// round 6
// speedup vs baseline: 1.7230x; 1.7230x over previous
#include <cuda_runtime.h>

#define NIN 7
#define H   32
#define TPB 128   // threads per block
#define SPT 2     // samples per thread

typedef unsigned long long u64;

// Constant-bank weight image, float4-granular:
//  [0,56)    w0t  : w0t[i*8+c] covers floats i*32 + 4c .. +3  (w0 transposed [i][h])
//  [56,312)  w1t  : w1t[i*8+c]                                 (w1 transposed [i][h])
//  [312,320) b0   (32 floats)
//  [320,328) b1   (32 floats)
//  [328,336) w2   (32 floats)
//  [336]     b2 in .x
__constant__ float4 CW4[337];
__device__ float DSTG[1348];

typedef union { float4 f; ulonglong2 u; } F4U;

__device__ __forceinline__ ulonglong2 ldc4(int idx) {
    F4U t; t.f = CW4[idx]; return t.u;
}

// ---- f32x2 packed helpers (sm_100+ PTX) ----
__device__ __forceinline__ u64 pk2(float a, float b) {
    u64 r; asm("mov.b64 %0, {%1, %2};" : "=l"(r) : "f"(a), "f"(b)); return r;
}
__device__ __forceinline__ float2 upk2(u64 v) {
    float2 f; asm("mov.b64 {%0, %1}, %2;" : "=f"(f.x), "=f"(f.y) : "l"(v)); return f;
}
__device__ __forceinline__ u64 ffma2(u64 a, u64 b, u64 c) {
    u64 r; asm("fma.rn.f32x2 %0, %1, %2, %3;" : "=l"(r) : "l"(a), "l"(b), "l"(c)); return r;
}

// Single-instruction MUFU.TANH (sm_75+).
__device__ __forceinline__ float tanh_approx(float x) {
    float r; asm("tanh.approx.f32 %0, %1;" : "=f"(r) : "f"(x)); return r;
}

// Transpose weights into the staging layout (then memcpy'd into CW4).
__global__ void prep_kernel(const float* __restrict__ w0, const float* __restrict__ b0,
                            const float* __restrict__ w1, const float* __restrict__ b1,
                            const float* __restrict__ w2, const float* __restrict__ b2)
{
    int k = blockIdx.x * blockDim.x + threadIdx.x;
    if (k < 224) {                       // w0t[i*32+h] = w0[h][i]
        int i = k >> 5, h = k & 31;
        DSTG[k] = w0[h * NIN + i];
    } else if (k < 1248) {               // w1t[i*32+h] = w1[h][i]
        int kk = k - 224;
        int i = kk >> 5, h = kk & 31;
        DSTG[k] = w1[h * H + i];
    } else if (k < 1280) DSTG[k] = b0[k - 1248];
    else if (k < 1312)   DSTG[k] = b1[k - 1280];
    else if (k < 1344)   DSTG[k] = w2[k - 1312];
    else if (k < 1348)   DSTG[k] = b2[0];
}

__global__ __launch_bounds__(TPB, 4)
void WarpTileMLP_kernel(const float* __restrict__ q, float* __restrict__ out)
{
    const int tid = threadIdx.x;
    const long t = (long)blockIdx.x * TPB + tid;

    // 2 samples = 14 contiguous floats = 7 aligned float2 loads.
    const float2* qv = (const float2*)q;
    float v[14];
#pragma unroll
    for (int j = 0; j < 7; ++j) {
        float2 p = __ldg(&qv[t * 7 + j]);
        v[2 * j] = p.x; v[2 * j + 1] = p.y;
    }
    // sample A = v[0..6], sample B = v[7..13]

    // ---------------- Layer 0: 7 -> 32 (full width) ----------------
    u64 accA[16], accB[16];
#pragma unroll
    for (int pp = 0; pp < 8; ++pp) {
        ulonglong2 bb = ldc4(312 + pp);
        accA[2 * pp]     = bb.x; accB[2 * pp]     = bb.x;
        accA[2 * pp + 1] = bb.y; accB[2 * pp + 1] = bb.y;
    }
#pragma unroll
    for (int i = 0; i < NIN; ++i) {
        u64 xa = pk2(v[i], v[i]);
        u64 xb = pk2(v[7 + i], v[7 + i]);
#pragma unroll
        for (int c = 0; c < 8; ++c) {
            ulonglong2 w = ldc4(i * 8 + c);
            accA[2 * c]     = ffma2(w.x, xa, accA[2 * c]);
            accA[2 * c + 1] = ffma2(w.y, xa, accA[2 * c + 1]);
            accB[2 * c]     = ffma2(w.x, xb, accB[2 * c]);
            accB[2 * c + 1] = ffma2(w.y, xb, accB[2 * c + 1]);
        }
    }

    // tanh -> z (layer-0 accs die here)
    float zA[H], zB[H];
#pragma unroll
    for (int p = 0; p < 16; ++p) {
        float2 a = upk2(accA[p]);
        zA[2 * p] = tanh_approx(a.x); zA[2 * p + 1] = tanh_approx(a.y);
        float2 b = upk2(accB[p]);
        zB[2 * p] = tanh_approx(b.x); zB[2 * p + 1] = tanh_approx(b.y);
    }

    // ---- Layer 1 fused with Layer 2, in four quarters of 8 hidden units ----
    u64 oA = pk2(0.0f, 0.0f);
    u64 oB = pk2(0.0f, 0.0f);

#pragma unroll
    for (int qtr = 0; qtr < 4; ++qtr) {
        u64 a1A[4], a1B[4];
        {
            ulonglong2 b0p = ldc4(320 + qtr * 2);
            ulonglong2 b1p = ldc4(320 + qtr * 2 + 1);
            a1A[0] = b0p.x; a1A[1] = b0p.y; a1A[2] = b1p.x; a1A[3] = b1p.y;
            a1B[0] = b0p.x; a1B[1] = b0p.y; a1B[2] = b1p.x; a1B[3] = b1p.y;
        }
#pragma unroll
        for (int i = 0; i < H; ++i) {
            u64 xa = pk2(zA[i], zA[i]);
            u64 xb = pk2(zB[i], zB[i]);
#pragma unroll
            for (int c = 0; c < 2; ++c) {
                ulonglong2 w = ldc4(56 + i * 8 + qtr * 2 + c);
                a1A[2 * c]     = ffma2(w.x, xa, a1A[2 * c]);
                a1A[2 * c + 1] = ffma2(w.y, xa, a1A[2 * c + 1]);
                a1B[2 * c]     = ffma2(w.x, xb, a1B[2 * c]);
                a1B[2 * c + 1] = ffma2(w.y, xb, a1B[2 * c + 1]);
            }
        }
        // tanh + layer-2 partial dot (a1 dies here)
        ulonglong2 w2a = ldc4(328 + qtr * 2);
        ulonglong2 w2b = ldc4(328 + qtr * 2 + 1);
        u64 wps[4] = { w2a.x, w2a.y, w2b.x, w2b.y };
#pragma unroll
        for (int p = 0; p < 4; ++p) {
            u64 wp = wps[p];
            float2 a = upk2(a1A[p]);
            u64 za = pk2(tanh_approx(a.x), tanh_approx(a.y));
            oA = ffma2(wp, za, oA);
            float2 b = upk2(a1B[p]);
            u64 zb = pk2(tanh_approx(b.x), tanh_approx(b.y));
            oB = ffma2(wp, zb, oB);
        }
    }

    float2 ra = upk2(oA);
    float2 rb = upk2(oB);
    float bias2;
    { F4U tb; tb.f = CW4[336]; bias2 = tb.f.x; }
    float outA = ra.x + ra.y + bias2;
    float outB = rb.x + rb.y + bias2;

    ((float2*)out)[t] = make_float2(outA, outB);
}

extern "C" void kernel_launch(void* const* d_in, const int* in_sizes, int n_in,
                              void* d_out, int out_size)
{
    const float* q  = (const float*)d_in[0];
    const float* w0 = (const float*)d_in[1];
    const float* b0 = (const float*)d_in[2];
    const float* w1 = (const float*)d_in[3];
    const float* b1 = (const float*)d_in[4];
    const float* w2 = (const float*)d_in[5];
    const float* b2 = (const float*)d_in[6];
    float* out = (float*)d_out;

    // 1) transpose weights into staging (device global)
    prep_kernel<<<11, TPB>>>(w0, b0, w1, b1, w2, b2);

    // 2) copy staging -> constant bank (D2D memcpy node; graph-capturable)
    void* sym = nullptr; void* stg = nullptr;
    cudaGetSymbolAddress(&sym, CW4);
    cudaGetSymbolAddress(&stg, DSTG);
    cudaMemcpyAsync(sym, stg, 1348 * sizeof(float), cudaMemcpyDeviceToDevice);

    // 3) main kernel
    const int B = in_sizes[0] / NIN;              // 2097152
    const int blocks = B / (TPB * SPT);           // 8192
    WarpTileMLP_kernel<<<blocks, TPB>>>(q, out);
}